// round 4
// baseline (speedup 1.0000x reference)
#include <cuda_runtime.h>
#include <math.h>

// Problem constants
#define B_SZ   4
#define S_SZ   2048
#define T_TOK  (B_SZ * S_SZ)      // 8192 tokens
#define H_DIM  1024
#define F_DIM  2048
#define N_EXP  8
#define TOPK   2
#define NPAIR  (T_TOK * TOPK)     // 16384 token-expert pairs

#define OUT_ELEMS  (T_TOK * H_DIM)          // 8388608
#define RL_OFFSET  OUT_ELEMS                // router_logits after main out

// ---------------- device scratch (static: allocation rules) ----------------
__device__ float g_gated[(size_t)NPAIR * F_DIM];   // 128 MiB
__device__ float g_y[(size_t)NPAIR * H_DIM];       // 64 MiB
__device__ int   g_bucket[N_EXP * NPAIR];          // pair ids grouped by expert
__device__ int   g_cnt[N_EXP];
__device__ float g_wpair[NPAIR];                   // routing weight per pair

// ---------------- kernel 0: zero per-expert counters ----------------
__global__ void zero_cnt_kernel() {
    if (threadIdx.x < N_EXP) g_cnt[threadIdx.x] = 0;
}

// ---------------- kernel 1: router (logits, softmax-top2, buckets) ----------
// one warp per token; 8 warps / 256-thread block
__global__ void router_kernel(const float* __restrict__ x,
                              const float* __restrict__ gw,
                              float* __restrict__ rlogits) {
    int warp = (blockIdx.x * blockDim.x + threadIdx.x) >> 5;
    int lane = threadIdx.x & 31;
    if (warp >= T_TOK) return;

    const float* xr = x + (size_t)warp * H_DIM;
    float xv[32];
#pragma unroll
    for (int i = 0; i < 32; i++) xv[i] = xr[i * 32 + lane];

    float l[N_EXP];
#pragma unroll
    for (int e = 0; e < N_EXP; e++) {
        const float* g = gw + e * H_DIM;
        float s = 0.f;
#pragma unroll
        for (int i = 0; i < 32; i++) s += xv[i] * g[i * 32 + lane];
#pragma unroll
        for (int o = 16; o; o >>= 1) s += __shfl_xor_sync(0xffffffffu, s, o);
        l[e] = s;   // full value on every lane after xor-reduce
    }

    if (lane == 0) {
#pragma unroll
        for (int e = 0; e < N_EXP; e++) rlogits[(size_t)warp * N_EXP + e] = l[e];

        // top-2 (first index wins ties, matching jax top_k)
        int i0 = 0;
#pragma unroll
        for (int e = 1; e < N_EXP; e++) if (l[e] > l[i0]) i0 = e;
        int i1 = (i0 == 0) ? 1 : 0;
#pragma unroll
        for (int e = 0; e < N_EXP; e++) if (e != i0 && l[e] > l[i1]) i1 = e;

        // normalized weights of the two selected softmax probs:
        // w0 = 1/(1+exp(l1-l0)), w1 = 1-w0
        float e1 = expf(l[i1] - l[i0]);
        float w0 = 1.f / (1.f + e1);
        float w1 = e1 / (1.f + e1);

        int p0 = warp * 2, p1 = warp * 2 + 1;
        g_wpair[p0] = w0;
        g_wpair[p1] = w1;
        int pos0 = atomicAdd(&g_cnt[i0], 1);
        g_bucket[i0 * NPAIR + pos0] = p0;
        int pos1 = atomicAdd(&g_cnt[i1], 1);
        g_bucket[i1 * NPAIR + pos1] = p1;
    }
}

// ---------------- kernel 2: grouped GEMM1  gated = silu(X W1^T) * (X W3^T) --
// 64x64 tile, BK=16, 256 threads, each thread 4x4, dual accumulators.
__global__ __launch_bounds__(256) void gemm1_kernel(
    const float* __restrict__ x,
    const float* __restrict__ w1,
    const float* __restrict__ w3) {
    int e = blockIdx.z;
    int nrows = g_cnt[e];
    int mbase = blockIdx.y * 64;
    if (mbase >= nrows) return;
    int fbase = blockIdx.x * 64;

    __shared__ float As[16][64];
    __shared__ float B1s[16][64];
    __shared__ float B3s[16][64];
    __shared__ int rowpair[64];

    int tid = threadIdx.x;
    if (tid < 64) {
        int r = mbase + tid;
        rowpair[tid] = (r < nrows) ? g_bucket[e * NPAIR + r] : -1;
    }
    __syncthreads();

    int lr = tid >> 2;            // 0..63  (tile row loaded by this thread)
    int lc = (tid & 3) * 4;       // 0,4,8,12
    int tx = tid & 15, ty = tid >> 4;

    int myp = rowpair[lr];
    int tok = (myp >= 0) ? (myp >> 1) : 0;
    const float* xrow  = x + (size_t)tok * H_DIM;
    const float* w1row = w1 + ((size_t)e * F_DIM + fbase + lr) * H_DIM;
    const float* w3row = w3 + ((size_t)e * F_DIM + fbase + lr) * H_DIM;

    float acc1[4][4] = {}, acc3[4][4] = {};

    for (int k = 0; k < H_DIM; k += 16) {
        float4 xa = *(const float4*)(xrow + k + lc);
        float4 b1 = *(const float4*)(w1row + k + lc);
        float4 b3 = *(const float4*)(w3row + k + lc);
        __syncthreads();
        As[lc + 0][lr] = xa.x;  As[lc + 1][lr] = xa.y;
        As[lc + 2][lr] = xa.z;  As[lc + 3][lr] = xa.w;
        B1s[lc + 0][lr] = b1.x; B1s[lc + 1][lr] = b1.y;
        B1s[lc + 2][lr] = b1.z; B1s[lc + 3][lr] = b1.w;
        B3s[lc + 0][lr] = b3.x; B3s[lc + 1][lr] = b3.y;
        B3s[lc + 2][lr] = b3.z; B3s[lc + 3][lr] = b3.w;
        __syncthreads();
#pragma unroll
        for (int kk = 0; kk < 16; kk++) {
            float4 a  = *(const float4*)&As[kk][ty * 4];
            float4 f1 = *(const float4*)&B1s[kk][tx * 4];
            float4 f3 = *(const float4*)&B3s[kk][tx * 4];
            float av[4] = {a.x, a.y, a.z, a.w};
            float b1v[4] = {f1.x, f1.y, f1.z, f1.w};
            float b3v[4] = {f3.x, f3.y, f3.z, f3.w};
#pragma unroll
            for (int i = 0; i < 4; i++)
#pragma unroll
                for (int j = 0; j < 4; j++) {
                    acc1[i][j] += av[i] * b1v[j];
                    acc3[i][j] += av[i] * b3v[j];
                }
        }
    }

#pragma unroll
    for (int i = 0; i < 4; i++) {
        int r = ty * 4 + i;
        int p = rowpair[r];
        if (p < 0) continue;
        float4 gv;
        float c;
        c = acc1[i][0]; gv.x = (c / (1.f + expf(-c))) * acc3[i][0];
        c = acc1[i][1]; gv.y = (c / (1.f + expf(-c))) * acc3[i][1];
        c = acc1[i][2]; gv.z = (c / (1.f + expf(-c))) * acc3[i][2];
        c = acc1[i][3]; gv.w = (c / (1.f + expf(-c))) * acc3[i][3];
        *(float4*)(g_gated + (size_t)p * F_DIM + fbase + tx * 4) = gv;
    }
}

// ---------------- kernel 3: grouped GEMM2  y = gated @ W2^T -----------------
__global__ __launch_bounds__(256) void gemm2_kernel(
    const float* __restrict__ w2) {
    int e = blockIdx.z;
    int nrows = g_cnt[e];
    int mbase = blockIdx.y * 64;
    if (mbase >= nrows) return;
    int hbase = blockIdx.x * 64;

    __shared__ float As[16][64];
    __shared__ float Bs[16][64];
    __shared__ int rowpair[64];

    int tid = threadIdx.x;
    if (tid < 64) {
        int r = mbase + tid;
        rowpair[tid] = (r < nrows) ? g_bucket[e * NPAIR + r] : -1;
    }
    __syncthreads();

    int lr = tid >> 2;
    int lc = (tid & 3) * 4;
    int tx = tid & 15, ty = tid >> 4;

    int myp = rowpair[lr];
    int srcp = (myp >= 0) ? myp : 0;
    const float* arow = g_gated + (size_t)srcp * F_DIM;
    const float* brow = w2 + ((size_t)e * H_DIM + hbase + lr) * F_DIM;

    float acc[4][4] = {};

    for (int k = 0; k < F_DIM; k += 16) {
        float4 av4 = *(const float4*)(arow + k + lc);
        float4 bv4 = *(const float4*)(brow + k + lc);
        __syncthreads();
        As[lc + 0][lr] = av4.x; As[lc + 1][lr] = av4.y;
        As[lc + 2][lr] = av4.z; As[lc + 3][lr] = av4.w;
        Bs[lc + 0][lr] = bv4.x; Bs[lc + 1][lr] = bv4.y;
        Bs[lc + 2][lr] = bv4.z; Bs[lc + 3][lr] = bv4.w;
        __syncthreads();
#pragma unroll
        for (int kk = 0; kk < 16; kk++) {
            float4 a = *(const float4*)&As[kk][ty * 4];
            float4 b = *(const float4*)&Bs[kk][tx * 4];
            float av[4] = {a.x, a.y, a.z, a.w};
            float bv[4] = {b.x, b.y, b.z, b.w};
#pragma unroll
            for (int i = 0; i < 4; i++)
#pragma unroll
                for (int j = 0; j < 4; j++)
                    acc[i][j] += av[i] * bv[j];
        }
    }

#pragma unroll
    for (int i = 0; i < 4; i++) {
        int r = ty * 4 + i;
        int p = rowpair[r];
        if (p < 0) continue;
        float4 ov = {acc[i][0], acc[i][1], acc[i][2], acc[i][3]};
        *(float4*)(g_y + (size_t)p * H_DIM + hbase + tx * 4) = ov;
    }
}

// ---------------- kernel 4: weighted combine (no atomics) -------------------
__global__ void combine_kernel(float* __restrict__ out) {
    int idx = blockIdx.x * blockDim.x + threadIdx.x;   // over T*H/4 float4s
    if (idx >= T_TOK * H_DIM / 4) return;
    int t = idx / (H_DIM / 4);
    int h4 = idx - t * (H_DIM / 4);
    float w0 = g_wpair[2 * t];
    float w1 = g_wpair[2 * t + 1];
    float4 a = *(const float4*)(g_y + (size_t)(2 * t) * H_DIM + h4 * 4);
    float4 b = *(const float4*)(g_y + (size_t)(2 * t + 1) * H_DIM + h4 * 4);
    float4 o;
    o.x = w0 * a.x + w1 * b.x;
    o.y = w0 * a.y + w1 * b.y;
    o.z = w0 * a.z + w1 * b.z;
    o.w = w0 * a.w + w1 * b.w;
    ((float4*)out)[idx] = o;
}

// ---------------- launch ----------------------------------------------------
extern "C" void kernel_launch(void* const* d_in, const int* in_sizes, int n_in,
                              void* d_out, int out_size) {
    const float* hidden = (const float*)d_in[0];   // [B,S,H]
    const float* gate_w = (const float*)d_in[1];   // [E,H]
    const float* w1     = (const float*)d_in[2];   // [E,F,H]
    const float* w3     = (const float*)d_in[3];   // [E,F,H]
    const float* w2     = (const float*)d_in[4];   // [E,H,F]
    float* out = (float*)d_out;                    // [B,S,H] then [T,E] logits

    zero_cnt_kernel<<<1, 32>>>();
    router_kernel<<<T_TOK / 8, 256>>>(hidden, gate_w, out + RL_OFFSET);
    // worst case: one expert owns all 16384 pairs -> 256 row tiles; extra CTAs exit
    gemm1_kernel<<<dim3(F_DIM / 64, 256, N_EXP), 256>>>(hidden, w1, w3);
    gemm2_kernel<<<dim3(H_DIM / 64, 256, N_EXP), 256>>>(w2);
    combine_kernel<<<(T_TOK * H_DIM / 4 + 255) / 256, 256>>>(out);
}

// round 7
// speedup vs baseline: 3.3623x; 3.3623x over previous
#include <cuda_runtime.h>
#include <math.h>
#include <stdint.h>

// Problem constants
#define B_SZ   4
#define S_SZ   2048
#define T_TOK  (B_SZ * S_SZ)      // 8192 tokens
#define H_DIM  1024
#define F_DIM  2048
#define N_EXP  8
#define NPAIR  (T_TOK * 2)        // 16384 token-expert pairs

#define OUT_ELEMS  (T_TOK * H_DIM)
#define RL_OFFSET  OUT_ELEMS

// ---------------- device scratch (static: allocation rules) ----------------
__device__ float g_gated[(size_t)NPAIR * F_DIM];   // 128 MiB
__device__ float g_y[(size_t)NPAIR * H_DIM];       // 64 MiB
__device__ int   g_bucket[N_EXP * NPAIR];
__device__ int   g_cnt[N_EXP];
__device__ float g_wpair[NPAIR];

// =================== PTX helpers (baseline sm_80-class PTX only) ============
__device__ __forceinline__ uint32_t smem_u32(const void* p) {
    uint32_t a;
    asm("{ .reg .u64 t; cvta.to.shared.u64 t, %1; cvt.u32.u64 %0, t; }" : "=r"(a) : "l"(p));
    return a;
}
#define CP16(dst, src) asm volatile("cp.async.cg.shared.global [%0], [%1], 16;" :: "r"(dst), "l"(src))
#define CPCOMMIT()     asm volatile("cp.async.commit_group;")
#define CPWAIT(n)      asm volatile("cp.async.wait_group %0;" :: "n"(n))

__device__ __forceinline__ uint32_t f2tf(float f) {
    uint32_t r;
    asm("cvt.rna.tf32.f32 %0, %1;" : "=r"(r) : "f"(f));
    return r;
}

// D += A*B, m16n8k8 tf32, row.col, f32 accum
__device__ __forceinline__ void mma8(float* c, const uint32_t* a, const uint32_t* b) {
    asm volatile(
        "mma.sync.aligned.m16n8k8.row.col.f32.tf32.tf32.f32 "
        "{%0,%1,%2,%3}, {%4,%5,%6,%7}, {%8,%9}, {%0,%1,%2,%3};"
        : "+f"(c[0]), "+f"(c[1]), "+f"(c[2]), "+f"(c[3])
        : "r"(a[0]), "r"(a[1]), "r"(a[2]), "r"(a[3]), "r"(b[0]), "r"(b[1]));
}

// smem row stride in floats (32 data + 4 pad -> 144B rows, 16B aligned)
#define LDP 36

// =================== kernel 0: zero counters ===================
__global__ void zero_cnt_kernel() {
    if (threadIdx.x < N_EXP) g_cnt[threadIdx.x] = 0;
}

// =================== kernel 1: router ===================
__global__ void router_kernel(const float* __restrict__ x,
                              const float* __restrict__ gw,
                              float* __restrict__ rlogits) {
    int warp = (blockIdx.x * blockDim.x + threadIdx.x) >> 5;
    int lane = threadIdx.x & 31;
    if (warp >= T_TOK) return;

    const float* xr = x + (size_t)warp * H_DIM;
    float xv[32];
#pragma unroll
    for (int i = 0; i < 32; i++) xv[i] = xr[i * 32 + lane];

    float l[N_EXP];
#pragma unroll
    for (int e = 0; e < N_EXP; e++) {
        const float* g = gw + e * H_DIM;
        float s = 0.f;
#pragma unroll
        for (int i = 0; i < 32; i++) s += xv[i] * g[i * 32 + lane];
#pragma unroll
        for (int o = 16; o; o >>= 1) s += __shfl_xor_sync(0xffffffffu, s, o);
        l[e] = s;
    }

    if (lane == 0) {
#pragma unroll
        for (int e = 0; e < N_EXP; e++) rlogits[(size_t)warp * N_EXP + e] = l[e];

        int i0 = 0;
#pragma unroll
        for (int e = 1; e < N_EXP; e++) if (l[e] > l[i0]) i0 = e;
        int i1 = (i0 == 0) ? 1 : 0;
#pragma unroll
        for (int e = 0; e < N_EXP; e++) if (e != i0 && l[e] > l[i1]) i1 = e;

        float e1 = expf(l[i1] - l[i0]);
        float w0 = 1.f / (1.f + e1);
        float w1 = e1 / (1.f + e1);

        int p0 = warp * 2, p1 = warp * 2 + 1;
        g_wpair[p0] = w0;
        g_wpair[p1] = w1;
        int pos0 = atomicAdd(&g_cnt[i0], 1);
        g_bucket[i0 * NPAIR + pos0] = p0;
        int pos1 = atomicAdd(&g_cnt[i1], 1);
        g_bucket[i1 * NPAIR + pos1] = p1;
    }
}

// =================== kernel 2: GEMM1 (mma.sync tf32) ===================
// Per CTA: 128 pairs x 128 F-cols, BK=32, 8 warps (2x4), warp tile 64x32.
// Computes D1 = X W1^T and D3 = X W3^T, epilogue silu(D1)*D3 -> g_gated.
// smem: rowpair[128] ints, then 2 stages of (A | B1 | B3), each 128xLDP f32.
#define TILE_F   (128 * LDP)                 // floats per operand tile
#define G1_STAGE_F (3 * TILE_F)
#define G1_SMEM  (512 + 2 * G1_STAGE_F * 4)
#define G1_NCH   (H_DIM / 32)                // 32

__global__ __launch_bounds__(256, 1) void gemm1_mma(
    const float* __restrict__ x,
    const float* __restrict__ w1,
    const float* __restrict__ w3) {
    int e = blockIdx.z;
    int nrows = g_cnt[e];
    int mbase = blockIdx.y * 128;
    if (mbase >= nrows) return;
    int fbase = blockIdx.x * 128;

    extern __shared__ char smem[];
    int* rowpair = (int*)smem;
    float* stg[2];
    stg[0] = (float*)(smem + 512);
    stg[1] = stg[0] + G1_STAGE_F;

    int tid = threadIdx.x;
    int wid = tid >> 5, lane = tid & 31;
    int g = lane >> 2, tig = lane & 3;
    int wm = wid & 1, wn = wid >> 1;          // 2 x 4 warp grid

    if (tid < 128) {
        int r = mbase + tid;
        rowpair[tid] = (r < nrows) ? g_bucket[e * NPAIR + r] : -1;
    }
    __syncthreads();

    // ---- load mapping: thread loads 4 rows per operand, 16B each ----
    int trow = tid >> 3;                      // 0..31
    int tcf  = (tid & 7) * 4;                 // float col in 32-chunk
    uint32_t dsto = (uint32_t)(trow * LDP + tcf) * 4;  // byte offset in tile

    const float* aptr[4];
#pragma unroll
    for (int i = 0; i < 4; i++) {
        int rp = rowpair[i * 32 + trow];
        int tok = ((rp >= 0) ? rp : rowpair[0]) >> 1;
        aptr[i] = x + (size_t)tok * H_DIM + tcf;
    }
    const float* w1b = w1 + ((size_t)e * F_DIM + fbase) * H_DIM + tcf;
    const float* w3b = w3 + ((size_t)e * F_DIM + fbase) * H_DIM + tcf;
    size_t boff[4];
#pragma unroll
    for (int i = 0; i < 4; i++) boff[i] = (size_t)(i * 32 + trow) * H_DIM;

    uint32_t sA[2], sB1[2], sB3[2];
#pragma unroll
    for (int s = 0; s < 2; s++) {
        uint32_t base = smem_u32(stg[s]);
        sA[s]  = base + dsto;
        sB1[s] = base + TILE_F * 4 + dsto;
        sB3[s] = base + 2 * TILE_F * 4 + dsto;
    }

    float acc1[4][4][4] = {}, acc3[4][4][4] = {};

    auto load_chunk = [&](int c, int s) {
        int ko = c * 32;
#pragma unroll
        for (int i = 0; i < 4; i++) {
            CP16(sA[s]  + i * 32 * LDP * 4, aptr[i] + ko);
            CP16(sB1[s] + i * 32 * LDP * 4, w1b + boff[i] + ko);
            CP16(sB3[s] + i * 32 * LDP * 4, w3b + boff[i] + ko);
        }
        CPCOMMIT();
    };

    load_chunk(0, 0);
    for (int c = 0; c < G1_NCH; c++) {
        int s = c & 1;
        if (c + 1 < G1_NCH) { load_chunk(c + 1, s ^ 1); CPWAIT(1); }
        else                { CPWAIT(0); }
        __syncthreads();

        const float* As  = stg[s];
        const float* B1s = stg[s] + TILE_F;
        const float* B3s = stg[s] + 2 * TILE_F;
#pragma unroll
        for (int kk = 0; kk < 4; kk++) {
            uint32_t a[4][4];
#pragma unroll
            for (int mf = 0; mf < 4; mf++) {
                int r0 = wm * 64 + mf * 16 + g;
                a[mf][0] = f2tf(As[r0 * LDP + kk * 8 + tig]);
                a[mf][1] = f2tf(As[(r0 + 8) * LDP + kk * 8 + tig]);
                a[mf][2] = f2tf(As[r0 * LDP + kk * 8 + tig + 4]);
                a[mf][3] = f2tf(As[(r0 + 8) * LDP + kk * 8 + tig + 4]);
            }
            uint32_t b1[4][2], b3[4][2];
#pragma unroll
            for (int nf = 0; nf < 4; nf++) {
                int n0 = wn * 32 + nf * 8 + g;
                b1[nf][0] = f2tf(B1s[n0 * LDP + kk * 8 + tig]);
                b1[nf][1] = f2tf(B1s[n0 * LDP + kk * 8 + tig + 4]);
                b3[nf][0] = f2tf(B3s[n0 * LDP + kk * 8 + tig]);
                b3[nf][1] = f2tf(B3s[n0 * LDP + kk * 8 + tig + 4]);
            }
#pragma unroll
            for (int mf = 0; mf < 4; mf++)
#pragma unroll
                for (int nf = 0; nf < 4; nf++) {
                    mma8(acc1[mf][nf], a[mf], b1[nf]);
                    mma8(acc3[mf][nf], a[mf], b3[nf]);
                }
        }
        __syncthreads();
    }

    // epilogue: silu(acc1)*acc3 -> g_gated
#pragma unroll
    for (int mf = 0; mf < 4; mf++) {
#pragma unroll
        for (int half = 0; half < 2; half++) {
            int row = wm * 64 + mf * 16 + g + half * 8;
            int p = rowpair[row];
            if (p < 0) continue;
            float* dst = g_gated + (size_t)p * F_DIM + fbase;
#pragma unroll
            for (int nf = 0; nf < 4; nf++) {
                int col = wn * 32 + nf * 8 + tig * 2;
                float c0 = acc1[mf][nf][half * 2 + 0];
                float c1 = acc1[mf][nf][half * 2 + 1];
                float g0 = acc3[mf][nf][half * 2 + 0];
                float g1 = acc3[mf][nf][half * 2 + 1];
                float2 o;
                o.x = c0 / (1.f + expf(-c0)) * g0;
                o.y = c1 / (1.f + expf(-c1)) * g1;
                *(float2*)(dst + col) = o;
            }
        }
    }
}

// =================== kernel 3: GEMM2 (mma.sync tf32) ===================
// Per CTA: 128 pairs x 128 H-cols, K = F_DIM.
#define G2_STAGE_F (2 * TILE_F)
#define G2_SMEM  (512 + 2 * G2_STAGE_F * 4)
#define G2_NCH   (F_DIM / 32)                // 64

__global__ __launch_bounds__(256, 2) void gemm2_mma(const float* __restrict__ w2) {
    int e = blockIdx.z;
    int nrows = g_cnt[e];
    int mbase = blockIdx.y * 128;
    if (mbase >= nrows) return;
    int hbase = blockIdx.x * 128;

    extern __shared__ char smem[];
    int* rowpair = (int*)smem;
    float* stg[2];
    stg[0] = (float*)(smem + 512);
    stg[1] = stg[0] + G2_STAGE_F;

    int tid = threadIdx.x;
    int wid = tid >> 5, lane = tid & 31;
    int g = lane >> 2, tig = lane & 3;
    int wm = wid & 1, wn = wid >> 1;

    if (tid < 128) {
        int r = mbase + tid;
        rowpair[tid] = (r < nrows) ? g_bucket[e * NPAIR + r] : -1;
    }
    __syncthreads();

    int trow = tid >> 3;
    int tcf  = (tid & 7) * 4;
    uint32_t dsto = (uint32_t)(trow * LDP + tcf) * 4;

    const float* aptr[4];
#pragma unroll
    for (int i = 0; i < 4; i++) {
        int rp = rowpair[i * 32 + trow];
        int pr = (rp >= 0) ? rp : rowpair[0];
        aptr[i] = g_gated + (size_t)pr * F_DIM + tcf;
    }
    const float* w2b = w2 + ((size_t)e * H_DIM + hbase) * F_DIM + tcf;
    size_t boff[4];
#pragma unroll
    for (int i = 0; i < 4; i++) boff[i] = (size_t)(i * 32 + trow) * F_DIM;

    uint32_t sA[2], sB[2];
#pragma unroll
    for (int s = 0; s < 2; s++) {
        uint32_t base = smem_u32(stg[s]);
        sA[s] = base + dsto;
        sB[s] = base + TILE_F * 4 + dsto;
    }

    float acc[4][4][4] = {};

    auto load_chunk = [&](int c, int s) {
        int ko = c * 32;
#pragma unroll
        for (int i = 0; i < 4; i++) {
            CP16(sA[s] + i * 32 * LDP * 4, aptr[i] + ko);
            CP16(sB[s] + i * 32 * LDP * 4, w2b + boff[i] + ko);
        }
        CPCOMMIT();
    };

    load_chunk(0, 0);
    for (int c = 0; c < G2_NCH; c++) {
        int s = c & 1;
        if (c + 1 < G2_NCH) { load_chunk(c + 1, s ^ 1); CPWAIT(1); }
        else                { CPWAIT(0); }
        __syncthreads();

        const float* As = stg[s];
        const float* Bs = stg[s] + TILE_F;
#pragma unroll
        for (int kk = 0; kk < 4; kk++) {
            uint32_t a[4][4];
#pragma unroll
            for (int mf = 0; mf < 4; mf++) {
                int r0 = wm * 64 + mf * 16 + g;
                a[mf][0] = f2tf(As[r0 * LDP + kk * 8 + tig]);
                a[mf][1] = f2tf(As[(r0 + 8) * LDP + kk * 8 + tig]);
                a[mf][2] = f2tf(As[r0 * LDP + kk * 8 + tig + 4]);
                a[mf][3] = f2tf(As[(r0 + 8) * LDP + kk * 8 + tig + 4]);
            }
            uint32_t b[4][2];
#pragma unroll
            for (int nf = 0; nf < 4; nf++) {
                int n0 = wn * 32 + nf * 8 + g;
                b[nf][0] = f2tf(Bs[n0 * LDP + kk * 8 + tig]);
                b[nf][1] = f2tf(Bs[n0 * LDP + kk * 8 + tig + 4]);
            }
#pragma unroll
            for (int mf = 0; mf < 4; mf++)
#pragma unroll
                for (int nf = 0; nf < 4; nf++)
                    mma8(acc[mf][nf], a[mf], b[nf]);
        }
        __syncthreads();
    }

#pragma unroll
    for (int mf = 0; mf < 4; mf++) {
#pragma unroll
        for (int half = 0; half < 2; half++) {
            int row = wm * 64 + mf * 16 + g + half * 8;
            int p = rowpair[row];
            if (p < 0) continue;
            float* dst = g_y + (size_t)p * H_DIM + hbase;
#pragma unroll
            for (int nf = 0; nf < 4; nf++) {
                int col = wn * 32 + nf * 8 + tig * 2;
                float2 o;
                o.x = acc[mf][nf][half * 2 + 0];
                o.y = acc[mf][nf][half * 2 + 1];
                *(float2*)(dst + col) = o;
            }
        }
    }
}

// =================== kernel 4: weighted combine ===================
__global__ void combine_kernel(float* __restrict__ out) {
    int idx = blockIdx.x * blockDim.x + threadIdx.x;
    if (idx >= T_TOK * H_DIM / 4) return;
    int t = idx / (H_DIM / 4);
    int h4 = idx - t * (H_DIM / 4);
    float w0 = g_wpair[2 * t];
    float w1 = g_wpair[2 * t + 1];
    float4 a = *(const float4*)(g_y + (size_t)(2 * t) * H_DIM + h4 * 4);
    float4 b = *(const float4*)(g_y + (size_t)(2 * t + 1) * H_DIM + h4 * 4);
    float4 o;
    o.x = w0 * a.x + w1 * b.x;
    o.y = w0 * a.y + w1 * b.y;
    o.z = w0 * a.z + w1 * b.z;
    o.w = w0 * a.w + w1 * b.w;
    ((float4*)out)[idx] = o;
}

// =================== launch ===================
extern "C" void kernel_launch(void* const* d_in, const int* in_sizes, int n_in,
                              void* d_out, int out_size) {
    const float* hidden = (const float*)d_in[0];
    const float* gate_w = (const float*)d_in[1];
    const float* w1     = (const float*)d_in[2];
    const float* w3     = (const float*)d_in[3];
    const float* w2     = (const float*)d_in[4];
    float* out = (float*)d_out;

    static int attr_done = 0;
    if (!attr_done) {
        cudaFuncSetAttribute(gemm1_mma, cudaFuncAttributeMaxDynamicSharedMemorySize, G1_SMEM);
        cudaFuncSetAttribute(gemm2_mma, cudaFuncAttributeMaxDynamicSharedMemorySize, G2_SMEM);
        attr_done = 1;
    }

    zero_cnt_kernel<<<1, 32>>>();
    router_kernel<<<T_TOK / 8, 256>>>(hidden, gate_w, out + RL_OFFSET);
    // worst case one expert owns all NPAIR pairs -> NPAIR/128 = 128 M-tiles
    gemm1_mma<<<dim3(F_DIM / 128, NPAIR / 128, N_EXP), 256, G1_SMEM>>>(hidden, w1, w3);
    gemm2_mma<<<dim3(H_DIM / 128, NPAIR / 128, N_EXP), 256, G2_SMEM>>>(w2);
    combine_kernel<<<(T_TOK * H_DIM / 4 + 255) / 256, 256>>>(out);
}

// round 8
// speedup vs baseline: 5.7111x; 1.6986x over previous
#include <cuda_runtime.h>
#include <cuda_fp16.h>
#include <math.h>
#include <stdint.h>

// Problem constants
#define T_TOK  8192
#define H_DIM  1024
#define F_DIM  2048
#define N_EXP  8
#define NPAIR  16384

#define OUT_ELEMS  (T_TOK * H_DIM)
#define RL_OFFSET  OUT_ELEMS

// ---------------- device scratch (static: allocation rules) ----------------
__device__ __half g_xh[(size_t)T_TOK * H_DIM];            // 16.8 MB
__device__ __half g_w1h[(size_t)N_EXP * F_DIM * H_DIM];   // 33.5 MB
__device__ __half g_w3h[(size_t)N_EXP * F_DIM * H_DIM];   // 33.5 MB
__device__ __half g_w2h[(size_t)N_EXP * H_DIM * F_DIM];   // 33.5 MB
__device__ __half g_gatedh[(size_t)NPAIR * F_DIM];        // 67 MB
__device__ float  g_y[(size_t)NPAIR * H_DIM];             // 67 MB
__device__ int    g_bucket[N_EXP * NPAIR];
__device__ int    g_cnt[N_EXP];
__device__ float  g_wpair[NPAIR];

// =================== PTX helpers (baseline sm_80-class PTX) ===================
__device__ __forceinline__ uint32_t smem_u32(const void* p) {
    uint32_t a;
    asm("{ .reg .u64 t; cvta.to.shared.u64 t, %1; cvt.u32.u64 %0, t; }" : "=r"(a) : "l"(p));
    return a;
}
#define CP16(dst, src) asm volatile("cp.async.cg.shared.global [%0], [%1], 16;" :: "r"(dst), "l"(src))
#define CPCOMMIT()     asm volatile("cp.async.commit_group;")
#define CPWAIT(n)      asm volatile("cp.async.wait_group %0;" :: "n"(n))

__device__ __forceinline__ void ldm_x4(uint32_t* r, uint32_t addr) {
    asm volatile("ldmatrix.sync.aligned.m8n8.x4.shared.b16 {%0,%1,%2,%3}, [%4];"
        : "=r"(r[0]), "=r"(r[1]), "=r"(r[2]), "=r"(r[3]) : "r"(addr));
}
// D += A*B, m16n8k16 fp16 in, f32 accum
__device__ __forceinline__ void mma16(float* c, const uint32_t* a, uint32_t b0, uint32_t b1) {
    asm volatile(
        "mma.sync.aligned.m16n8k16.row.col.f32.f16.f16.f32 "
        "{%0,%1,%2,%3}, {%4,%5,%6,%7}, {%8,%9}, {%0,%1,%2,%3};"
        : "+f"(c[0]), "+f"(c[1]), "+f"(c[2]), "+f"(c[3])
        : "r"(a[0]), "r"(a[1]), "r"(a[2]), "r"(a[3]), "r"(b0), "r"(b1));
}

// smem tile layout: 128B rows (64 halfs = one BK=64 K-chunk).
// phys offset of logical (row, 16B-unit u) = row*128 + ((u ^ (row&7))<<4)

// =================== kernel 0: zero counters ===================
__global__ void zero_cnt_kernel() {
    if (threadIdx.x < N_EXP) g_cnt[threadIdx.x] = 0;
}

// =================== kernel: f32 -> f16 (rne) bulk convert ===================
__global__ void f2h_kernel(const float4* __restrict__ src, uint2* __restrict__ dst, int n4) {
    int i = blockIdx.x * blockDim.x + threadIdx.x;
    if (i >= n4) return;
    float4 v = src[i];
    __half2 h0 = __floats2half2_rn(v.x, v.y);
    __half2 h1 = __floats2half2_rn(v.z, v.w);
    uint2 o;
    o.x = *reinterpret_cast<uint32_t*>(&h0);
    o.y = *reinterpret_cast<uint32_t*>(&h1);
    dst[i] = o;
}

// =================== kernel 1: router (f32, exact) ===================
__global__ void router_kernel(const float* __restrict__ x,
                              const float* __restrict__ gw,
                              float* __restrict__ rlogits) {
    int warp = (blockIdx.x * blockDim.x + threadIdx.x) >> 5;
    int lane = threadIdx.x & 31;
    if (warp >= T_TOK) return;

    const float* xr = x + (size_t)warp * H_DIM;
    float xv[32];
#pragma unroll
    for (int i = 0; i < 32; i++) xv[i] = xr[i * 32 + lane];

    float l[N_EXP];
#pragma unroll
    for (int e = 0; e < N_EXP; e++) {
        const float* g = gw + e * H_DIM;
        float s = 0.f;
#pragma unroll
        for (int i = 0; i < 32; i++) s += xv[i] * g[i * 32 + lane];
#pragma unroll
        for (int o = 16; o; o >>= 1) s += __shfl_xor_sync(0xffffffffu, s, o);
        l[e] = s;
    }

    if (lane == 0) {
#pragma unroll
        for (int e = 0; e < N_EXP; e++) rlogits[(size_t)warp * N_EXP + e] = l[e];

        int i0 = 0;
#pragma unroll
        for (int e = 1; e < N_EXP; e++) if (l[e] > l[i0]) i0 = e;
        int i1 = (i0 == 0) ? 1 : 0;
#pragma unroll
        for (int e = 0; e < N_EXP; e++) if (e != i0 && l[e] > l[i1]) i1 = e;

        float e1 = expf(l[i1] - l[i0]);
        float w0 = 1.f / (1.f + e1);
        float w1 = e1 / (1.f + e1);

        int p0 = warp * 2, p1 = warp * 2 + 1;
        g_wpair[p0] = w0;
        g_wpair[p1] = w1;
        int pos0 = atomicAdd(&g_cnt[i0], 1);
        g_bucket[i0 * NPAIR + pos0] = p0;
        int pos1 = atomicAdd(&g_cnt[i1], 1);
        g_bucket[i1 * NPAIR + pos1] = p1;
    }
}

// =================== kernel 2: GEMM1 fp16 mma ===================
// CTA: 128 pairs x 64 F-cols, BK=64. Computes D1 = X W1^T and D3 = X W3^T,
// epilogue silu(D1)*D3 -> g_gatedh (fp16).
// 8 warps: wm = wid&3 (m32 tiles), wn = wid>>2 (n32 tiles over 64 cols).
// smem stage (32KB): A 128x128B @0, B1 64x128B @16K, B3 @24K. 2 stages.
#define G1_STAGE 32768
#define G1_SMEM  (512 + 2 * G1_STAGE)
#define G1_NCH   (H_DIM / 64)    // 16

__global__ __launch_bounds__(256, 2) void gemm1_h() {
    int e = blockIdx.z;
    int nrows = g_cnt[e];
    int mbase = blockIdx.y * 128;
    if (mbase >= nrows) return;
    int fbase = blockIdx.x * 64;

    extern __shared__ char smem[];
    int* rowpair = (int*)smem;
    uint32_t sb = smem_u32(smem + 512);

    int tid = threadIdx.x;
    int wid = tid >> 5, lane = tid & 31;
    int g = lane >> 2, tig = lane & 3;
    int wm = wid & 3, wn = wid >> 2;

    if (tid < 128) {
        int r = mbase + tid;
        rowpair[tid] = (r < nrows) ? g_bucket[e * NPAIR + r] : -1;
    }
    __syncthreads();

    // ---- cp.async mapping: 16B units, row = unit>>3, u = unit&7 ----
    int trow8 = tid >> 3, tu = tid & 7;
    const __half* aptr[4];
    uint32_t dstA[4];
#pragma unroll
    for (int q = 0; q < 4; q++) {
        int rq = q * 32 + trow8;
        int rp = rowpair[rq];
        int tok = ((rp >= 0) ? rp : rowpair[0]) >> 1;
        aptr[q] = g_xh + (size_t)tok * H_DIM + tu * 8;
        dstA[q] = (uint32_t)(rq * 128 + ((tu ^ (rq & 7)) << 4));
    }
    const __half *b1p[2], *b3p[2];
    uint32_t dstB[2];
#pragma unroll
    for (int j = 0; j < 2; j++) {
        int rb = j * 32 + trow8;
        b1p[j] = g_w1h + ((size_t)e * F_DIM + fbase + rb) * H_DIM + tu * 8;
        b3p[j] = g_w3h + ((size_t)e * F_DIM + fbase + rb) * H_DIM + tu * 8;
        dstB[j] = (uint32_t)(rb * 128 + ((tu ^ (rb & 7)) << 4));
    }

    auto load_chunk = [&](int c, int s) {
        uint32_t base = sb + s * G1_STAGE;
        int ko = c * 64;
#pragma unroll
        for (int q = 0; q < 4; q++) CP16(base + dstA[q], aptr[q] + ko);
#pragma unroll
        for (int j = 0; j < 2; j++) {
            CP16(base + 16384 + dstB[j], b1p[j] + ko);
            CP16(base + 24576 + dstB[j], b3p[j] + ko);
        }
        CPCOMMIT();
    };

    // ldmatrix lane mapping
    int lro = ((lane >> 3) & 1) * 8 + (lane & 7);
    int hi = lane >> 4;

    float acc1[2][4][4] = {}, acc3[2][4][4] = {};

    load_chunk(0, 0);
    for (int c = 0; c < G1_NCH; c++) {
        int s = c & 1;
        if (c + 1 < G1_NCH) { load_chunk(c + 1, s ^ 1); CPWAIT(1); }
        else                { CPWAIT(0); }
        __syncthreads();

        uint32_t aT = sb + s * G1_STAGE;
        uint32_t b1T = aT + 16384, b3T = aT + 24576;
#pragma unroll
        for (int kk = 0; kk < 4; kk++) {
            uint32_t af[2][4];
#pragma unroll
            for (int mf = 0; mf < 2; mf++) {
                int lr = wm * 32 + mf * 16 + lro;
                ldm_x4(af[mf], aT + lr * 128 + ((((kk * 2 + hi)) ^ (lr & 7)) << 4));
            }
            uint32_t bf1[2][4], bf3[2][4];
#pragma unroll
            for (int j = 0; j < 2; j++) {
                int lr = wn * 32 + j * 16 + lro;
                uint32_t ao = lr * 128 + ((((kk * 2 + hi)) ^ (lr & 7)) << 4);
                ldm_x4(bf1[j], b1T + ao);
                ldm_x4(bf3[j], b3T + ao);
            }
#pragma unroll
            for (int mf = 0; mf < 2; mf++)
#pragma unroll
                for (int nf = 0; nf < 4; nf++) {
                    int j = nf >> 1, w = nf & 1;
                    mma16(acc1[mf][nf], af[mf], bf1[j][w], bf1[j][w + 2]);
                    mma16(acc3[mf][nf], af[mf], bf3[j][w], bf3[j][w + 2]);
                }
        }
        __syncthreads();
    }

    // epilogue: silu(acc1)*acc3 -> g_gatedh (fp16)
#pragma unroll
    for (int mf = 0; mf < 2; mf++) {
#pragma unroll
        for (int hh = 0; hh < 2; hh++) {
            int row = wm * 32 + mf * 16 + g + hh * 8;
            int p = rowpair[row];
            if (p < 0) continue;
            __half* dst = g_gatedh + (size_t)p * F_DIM + fbase;
#pragma unroll
            for (int nf = 0; nf < 4; nf++) {
                int col = wn * 32 + nf * 8 + tig * 2;
                float c0 = acc1[mf][nf][hh * 2 + 0];
                float c1 = acc1[mf][nf][hh * 2 + 1];
                float g0 = acc3[mf][nf][hh * 2 + 0];
                float g1 = acc3[mf][nf][hh * 2 + 1];
                float o0 = c0 / (1.f + expf(-c0)) * g0;
                float o1 = c1 / (1.f + expf(-c1)) * g1;
                *(__half2*)(dst + col) = __floats2half2_rn(o0, o1);
            }
        }
    }
}

// =================== kernel 3: GEMM2 fp16 mma ===================
// CTA: 128 pairs x 128 H-cols, BK=64, K=F_DIM.
// 8 warps: wm = wid&1 (m64 tiles), wn = wid>>1 (n32 tiles over 128 cols).
// smem stage (32KB): A 128x128B @0, B 128x128B... B tile is 128 rows x 64
// halfs = 16KB @16K. 2 stages.
#define G2_STAGE 32768
#define G2_SMEM  (512 + 2 * G2_STAGE)
#define G2_NCH   (F_DIM / 64)    // 32

__global__ __launch_bounds__(256, 2) void gemm2_h() {
    int e = blockIdx.z;
    int nrows = g_cnt[e];
    int mbase = blockIdx.y * 128;
    if (mbase >= nrows) return;
    int hbase = blockIdx.x * 128;

    extern __shared__ char smem[];
    int* rowpair = (int*)smem;
    uint32_t sb = smem_u32(smem + 512);

    int tid = threadIdx.x;
    int wid = tid >> 5, lane = tid & 31;
    int g = lane >> 2, tig = lane & 3;
    int wm = wid & 1, wn = wid >> 1;

    if (tid < 128) {
        int r = mbase + tid;
        rowpair[tid] = (r < nrows) ? g_bucket[e * NPAIR + r] : -1;
    }
    __syncthreads();

    int trow8 = tid >> 3, tu = tid & 7;
    const __half* aptr[4];
    uint32_t dstA[4];
    const __half* bptr[4];
    uint32_t dstB[4];
#pragma unroll
    for (int q = 0; q < 4; q++) {
        int rq = q * 32 + trow8;
        int rp = rowpair[rq];
        int pr = (rp >= 0) ? rp : rowpair[0];
        aptr[q] = g_gatedh + (size_t)pr * F_DIM + tu * 8;
        dstA[q] = (uint32_t)(rq * 128 + ((tu ^ (rq & 7)) << 4));
        bptr[q] = g_w2h + ((size_t)e * H_DIM + hbase + rq) * F_DIM + tu * 8;
        dstB[q] = dstA[q];
    }

    auto load_chunk = [&](int c, int s) {
        uint32_t base = sb + s * G2_STAGE;
        int ko = c * 64;
#pragma unroll
        for (int q = 0; q < 4; q++) {
            CP16(base + dstA[q], aptr[q] + ko);
            CP16(base + 16384 + dstB[q], bptr[q] + ko);
        }
        CPCOMMIT();
    };

    int lro = ((lane >> 3) & 1) * 8 + (lane & 7);
    int hi = lane >> 4;

    float acc[4][4][4] = {};

    load_chunk(0, 0);
    for (int c = 0; c < G2_NCH; c++) {
        int s = c & 1;
        if (c + 1 < G2_NCH) { load_chunk(c + 1, s ^ 1); CPWAIT(1); }
        else                { CPWAIT(0); }
        __syncthreads();

        uint32_t aT = sb + s * G2_STAGE;
        uint32_t bT = aT + 16384;
#pragma unroll
        for (int kk = 0; kk < 4; kk++) {
            uint32_t af[4][4];
#pragma unroll
            for (int mf = 0; mf < 4; mf++) {
                int lr = wm * 64 + mf * 16 + lro;
                ldm_x4(af[mf], aT + lr * 128 + ((((kk * 2 + hi)) ^ (lr & 7)) << 4));
            }
            uint32_t bf[2][4];
#pragma unroll
            for (int j = 0; j < 2; j++) {
                int lr = wn * 32 + j * 16 + lro;
                ldm_x4(bf[j], bT + lr * 128 + ((((kk * 2 + hi)) ^ (lr & 7)) << 4));
            }
#pragma unroll
            for (int mf = 0; mf < 4; mf++)
#pragma unroll
                for (int nf = 0; nf < 4; nf++) {
                    int j = nf >> 1, w = nf & 1;
                    mma16(acc[mf][nf], af[mf], bf[j][w], bf[j][w + 2]);
                }
        }
        __syncthreads();
    }

#pragma unroll
    for (int mf = 0; mf < 4; mf++) {
#pragma unroll
        for (int hh = 0; hh < 2; hh++) {
            int row = wm * 64 + mf * 16 + g + hh * 8;
            int p = rowpair[row];
            if (p < 0) continue;
            float* dst = g_y + (size_t)p * H_DIM + hbase;
#pragma unroll
            for (int nf = 0; nf < 4; nf++) {
                int col = wn * 32 + nf * 8 + tig * 2;
                float2 o;
                o.x = acc[mf][nf][hh * 2 + 0];
                o.y = acc[mf][nf][hh * 2 + 1];
                *(float2*)(dst + col) = o;
            }
        }
    }
}

// =================== kernel 4: weighted combine ===================
__global__ void combine_kernel(float* __restrict__ out) {
    int idx = blockIdx.x * blockDim.x + threadIdx.x;
    if (idx >= T_TOK * H_DIM / 4) return;
    int t = idx / (H_DIM / 4);
    int h4 = idx - t * (H_DIM / 4);
    float w0 = g_wpair[2 * t];
    float w1 = g_wpair[2 * t + 1];
    float4 a = *(const float4*)(g_y + (size_t)(2 * t) * H_DIM + h4 * 4);
    float4 b = *(const float4*)(g_y + (size_t)(2 * t + 1) * H_DIM + h4 * 4);
    float4 o;
    o.x = w0 * a.x + w1 * b.x;
    o.y = w0 * a.y + w1 * b.y;
    o.z = w0 * a.z + w1 * b.z;
    o.w = w0 * a.w + w1 * b.w;
    ((float4*)out)[idx] = o;
}

// =================== launch ===================
extern "C" void kernel_launch(void* const* d_in, const int* in_sizes, int n_in,
                              void* d_out, int out_size) {
    const float* hidden = (const float*)d_in[0];
    const float* gate_w = (const float*)d_in[1];
    const float* w1     = (const float*)d_in[2];
    const float* w3     = (const float*)d_in[3];
    const float* w2     = (const float*)d_in[4];
    float* out = (float*)d_out;

    static int attr_done = 0;
    if (!attr_done) {
        cudaFuncSetAttribute(gemm1_h, cudaFuncAttributeMaxDynamicSharedMemorySize, G1_SMEM);
        cudaFuncSetAttribute(gemm2_h, cudaFuncAttributeMaxDynamicSharedMemorySize, G2_SMEM);
        attr_done = 1;
    }

    // device-symbol addresses are host-resolvable only via cudaGetSymbolAddress;
    // cache them (host-side, deterministic)
    static void *p_xh = nullptr, *p_w1h, *p_w3h, *p_w2h;
    if (!p_xh) {
        cudaGetSymbolAddress(&p_xh, g_xh);
        cudaGetSymbolAddress(&p_w1h, g_w1h);
        cudaGetSymbolAddress(&p_w3h, g_w3h);
        cudaGetSymbolAddress(&p_w2h, g_w2h);
    }

    const int NW4 = (N_EXP * F_DIM * H_DIM) / 4;   // 4194304
    const int NX4 = (T_TOK * H_DIM) / 4;           // 2097152

    zero_cnt_kernel<<<1, 32>>>();
    f2h_kernel<<<NX4 / 256, 256>>>((const float4*)hidden, (uint2*)p_xh, NX4);
    f2h_kernel<<<NW4 / 256, 256>>>((const float4*)w1, (uint2*)p_w1h, NW4);
    f2h_kernel<<<NW4 / 256, 256>>>((const float4*)w3, (uint2*)p_w3h, NW4);
    f2h_kernel<<<NW4 / 256, 256>>>((const float4*)w2, (uint2*)p_w2h, NW4);
    router_kernel<<<T_TOK / 8, 256>>>(hidden, gate_w, out + RL_OFFSET);
    // worst case one expert owns all NPAIR pairs -> 128 M-tiles; extras exit
    gemm1_h<<<dim3(F_DIM / 64, NPAIR / 128, N_EXP), 256, G1_SMEM>>>();
    gemm2_h<<<dim3(H_DIM / 128, NPAIR / 128, N_EXP), 256, G2_SMEM>>>();
    combine_kernel<<<(T_TOK * H_DIM / 4 + 255) / 256, 256>>>(out);
}

// round 9
// speedup vs baseline: 7.1386x; 1.2500x over previous
#include <cuda_runtime.h>
#include <cuda_fp16.h>
#include <math.h>
#include <stdint.h>

// Problem constants
#define T_TOK  8192
#define H_DIM  1024
#define F_DIM  2048
#define N_EXP  8
#define NPAIR  16384

#define OUT_ELEMS  (T_TOK * H_DIM)
#define RL_OFFSET  OUT_ELEMS

// ---------------- device scratch (static: allocation rules) ----------------
__device__ __half g_xh[(size_t)T_TOK * H_DIM];
__device__ __half g_w1h[(size_t)N_EXP * F_DIM * H_DIM];
__device__ __half g_w3h[(size_t)N_EXP * F_DIM * H_DIM];
__device__ __half g_w2h[(size_t)N_EXP * H_DIM * F_DIM];
__device__ __half g_gatedh[(size_t)NPAIR * F_DIM];
__device__ float  g_y[(size_t)NPAIR * H_DIM];
__device__ int    g_bucket[N_EXP * NPAIR];
__device__ int    g_cnt[N_EXP];
__device__ float  g_wpair[NPAIR];

// =================== PTX helpers (baseline sm_80-class PTX) ===================
__device__ __forceinline__ uint32_t smem_u32(const void* p) {
    uint32_t a;
    asm("{ .reg .u64 t; cvta.to.shared.u64 t, %1; cvt.u32.u64 %0, t; }" : "=r"(a) : "l"(p));
    return a;
}
#define CP16(dst, src) asm volatile("cp.async.cg.shared.global [%0], [%1], 16;" :: "r"(dst), "l"(src))
#define CPCOMMIT()     asm volatile("cp.async.commit_group;")
#define CPWAIT(n)      asm volatile("cp.async.wait_group %0;" :: "n"(n))

__device__ __forceinline__ void ldm_x4(uint32_t* r, uint32_t addr) {
    asm volatile("ldmatrix.sync.aligned.m8n8.x4.shared.b16 {%0,%1,%2,%3}, [%4];"
        : "=r"(r[0]), "=r"(r[1]), "=r"(r[2]), "=r"(r[3]) : "r"(addr));
}
__device__ __forceinline__ void mma16(float* c, const uint32_t* a, uint32_t b0, uint32_t b1) {
    asm volatile(
        "mma.sync.aligned.m16n8k16.row.col.f32.f16.f16.f32 "
        "{%0,%1,%2,%3}, {%4,%5,%6,%7}, {%8,%9}, {%0,%1,%2,%3};"
        : "+f"(c[0]), "+f"(c[1]), "+f"(c[2]), "+f"(c[3])
        : "r"(a[0]), "r"(a[1]), "r"(a[2]), "r"(a[3]), "r"(b0), "r"(b1));
}
// smem tile rows are 128B (64 halfs = BK chunk); phys(row, 16B-unit u) =
// row*128 + ((u ^ (row&7))<<4)  -> conflict-free cp.async + ldmatrix

// =================== kernel 0: zero counters ===================
__global__ void zero_cnt_kernel() {
    if (threadIdx.x < N_EXP) g_cnt[threadIdx.x] = 0;
}

// =================== f32 -> f16 (rne) bulk convert ===================
__global__ void f2h_kernel(const float4* __restrict__ src, uint2* __restrict__ dst, int n4) {
    int i = blockIdx.x * blockDim.x + threadIdx.x;
    if (i >= n4) return;
    float4 v = src[i];
    __half2 h0 = __floats2half2_rn(v.x, v.y);
    __half2 h1 = __floats2half2_rn(v.z, v.w);
    uint2 o;
    o.x = *reinterpret_cast<uint32_t*>(&h0);
    o.y = *reinterpret_cast<uint32_t*>(&h1);
    dst[i] = o;
}

// =================== kernel 1: router (f32, exact) ===================
__global__ void router_kernel(const float* __restrict__ x,
                              const float* __restrict__ gw,
                              float* __restrict__ rlogits) {
    int warp = (blockIdx.x * blockDim.x + threadIdx.x) >> 5;
    int lane = threadIdx.x & 31;
    if (warp >= T_TOK) return;

    const float* xr = x + (size_t)warp * H_DIM;
    float xv[32];
#pragma unroll
    for (int i = 0; i < 32; i++) xv[i] = xr[i * 32 + lane];

    float l[N_EXP];
#pragma unroll
    for (int e = 0; e < N_EXP; e++) {
        const float* g = gw + e * H_DIM;
        float s = 0.f;
#pragma unroll
        for (int i = 0; i < 32; i++) s += xv[i] * g[i * 32 + lane];
#pragma unroll
        for (int o = 16; o; o >>= 1) s += __shfl_xor_sync(0xffffffffu, s, o);
        l[e] = s;
    }

    if (lane == 0) {
#pragma unroll
        for (int e = 0; e < N_EXP; e++) rlogits[(size_t)warp * N_EXP + e] = l[e];

        int i0 = 0;
#pragma unroll
        for (int e = 1; e < N_EXP; e++) if (l[e] > l[i0]) i0 = e;
        int i1 = (i0 == 0) ? 1 : 0;
#pragma unroll
        for (int e = 0; e < N_EXP; e++) if (e != i0 && l[e] > l[i1]) i1 = e;

        float e1 = expf(l[i1] - l[i0]);
        float w0 = 1.f / (1.f + e1);
        float w1 = e1 / (1.f + e1);

        int p0 = warp * 2, p1 = warp * 2 + 1;
        g_wpair[p0] = w0;
        g_wpair[p1] = w1;
        int pos0 = atomicAdd(&g_cnt[i0], 1);
        g_bucket[i0 * NPAIR + pos0] = p0;
        int pos1 = atomicAdd(&g_cnt[i1], 1);
        g_bucket[i1 * NPAIR + pos1] = p1;
    }
}

// =================== kernel 2: GEMM1 fp16 (256x64, BK=64, 3-stage) ==========
// CTA: 256 pairs x 64 F-cols. D1 = X W1^T, D3 = X W3^T, silu fuse -> g_gatedh.
// 512 threads = 16 warps (8m x 2n), warp tile 32x32.
// stage (48KB): A 256x128B @0, B1 64x128B @32K, B3 @40K. 3 stages.
#define G1_STAGE 49152
#define G1_SMEM  (1024 + 3 * G1_STAGE)
#define G1_NCH   (H_DIM / 64)    // 16

__global__ __launch_bounds__(512, 1) void gemm1_h() {
    int e = blockIdx.z;
    int nrows = g_cnt[e];
    int mbase = blockIdx.y * 256;
    if (mbase >= nrows) return;
    int fbase = blockIdx.x * 64;

    extern __shared__ char smem[];
    int* rowpair = (int*)smem;
    uint32_t sb = smem_u32(smem + 1024);

    int tid = threadIdx.x;
    int wid = tid >> 5, lane = tid & 31;
    int g = lane >> 2, tig = lane & 3;
    int wm = wid & 7, wn = wid >> 3;          // 8 x 2 warp grid

    if (tid < 256) {
        int r = mbase + tid;
        rowpair[tid] = (r < nrows) ? g_bucket[e * NPAIR + r] : -1;
    }
    __syncthreads();

    // cp.async mapping: trow = tid>>3 (0..63), tu = tid&7
    int trow = tid >> 3, tu = tid & 7;
    const __half* aptr[4];
    uint32_t dstA[4];
#pragma unroll
    for (int q = 0; q < 4; q++) {
        int rq = q * 64 + trow;
        int rp = rowpair[rq];
        int tok = ((rp >= 0) ? rp : rowpair[0]) >> 1;
        aptr[q] = g_xh + (size_t)tok * H_DIM + tu * 8;
        dstA[q] = (uint32_t)(rq * 128 + ((tu ^ (rq & 7)) << 4));
    }
    const __half* b1p = g_w1h + ((size_t)e * F_DIM + fbase + trow) * H_DIM + tu * 8;
    const __half* b3p = g_w3h + ((size_t)e * F_DIM + fbase + trow) * H_DIM + tu * 8;
    uint32_t dstB = (uint32_t)(trow * 128 + ((tu ^ (trow & 7)) << 4));

    auto load_chunk = [&](int c, int s) {
        uint32_t base = sb + s * G1_STAGE;
        int ko = c * 64;
#pragma unroll
        for (int q = 0; q < 4; q++) CP16(base + dstA[q], aptr[q] + ko);
        CP16(base + 32768 + dstB, b1p + ko);
        CP16(base + 40960 + dstB, b3p + ko);
        CPCOMMIT();
    };

    int lro = ((lane >> 3) & 1) * 8 + (lane & 7);
    int hi = lane >> 4;

    float acc1[2][4][4] = {}, acc3[2][4][4] = {};

    load_chunk(0, 0);
    load_chunk(1, 1);
    for (int c = 0; c < G1_NCH; c++) {
        if (c > 0) __syncthreads();            // stage (c+2)%3 free to overwrite
        if (c + 2 < G1_NCH) load_chunk(c + 2, (c + 2) % 3);
        else                CPCOMMIT();        // keep group count uniform
        CPWAIT(2);
        __syncthreads();                       // chunk c visible to all warps

        uint32_t aT = sb + (c % 3) * G1_STAGE;
        uint32_t b1T = aT + 32768, b3T = aT + 40960;
#pragma unroll
        for (int kk = 0; kk < 4; kk++) {
            uint32_t af[2][4];
#pragma unroll
            for (int mf = 0; mf < 2; mf++) {
                int lr = wm * 32 + mf * 16 + lro;
                ldm_x4(af[mf], aT + lr * 128 + ((((kk * 2 + hi)) ^ (lr & 7)) << 4));
            }
            uint32_t bf1[2][4], bf3[2][4];
#pragma unroll
            for (int j = 0; j < 2; j++) {
                int lr = wn * 32 + j * 16 + lro;
                uint32_t ao = lr * 128 + ((((kk * 2 + hi)) ^ (lr & 7)) << 4);
                ldm_x4(bf1[j], b1T + ao);
                ldm_x4(bf3[j], b3T + ao);
            }
#pragma unroll
            for (int mf = 0; mf < 2; mf++)
#pragma unroll
                for (int nf = 0; nf < 4; nf++) {
                    int j = nf >> 1, w = nf & 1;
                    mma16(acc1[mf][nf], af[mf], bf1[j][w], bf1[j][w + 2]);
                    mma16(acc3[mf][nf], af[mf], bf3[j][w], bf3[j][w + 2]);
                }
        }
    }

    // epilogue: silu(acc1)*acc3 -> g_gatedh (fp16)
#pragma unroll
    for (int mf = 0; mf < 2; mf++) {
#pragma unroll
        for (int hh = 0; hh < 2; hh++) {
            int row = wm * 32 + mf * 16 + g + hh * 8;
            int p = rowpair[row];
            if (p < 0) continue;
            __half* dst = g_gatedh + (size_t)p * F_DIM + fbase;
#pragma unroll
            for (int nf = 0; nf < 4; nf++) {
                int col = wn * 32 + nf * 8 + tig * 2;
                float c0 = acc1[mf][nf][hh * 2 + 0];
                float c1 = acc1[mf][nf][hh * 2 + 1];
                float g0 = acc3[mf][nf][hh * 2 + 0];
                float g1 = acc3[mf][nf][hh * 2 + 1];
                float o0 = c0 / (1.f + expf(-c0)) * g0;
                float o1 = c1 / (1.f + expf(-c1)) * g1;
                *(__half2*)(dst + col) = __floats2half2_rn(o0, o1);
            }
        }
    }
}

// =================== kernel 3: GEMM2 fp16 (128x256, BK=64, 3-stage) =========
// CTA: 128 pairs x 256 H-cols, K = F_DIM.
// 512 threads = 16 warps (4m x 4n), warp tile 32x64.
// stage (48KB): A 128x128B @0, B 256x128B @16K. 3 stages.
#define G2_STAGE 49152
#define G2_SMEM  (1024 + 3 * G2_STAGE)
#define G2_NCH   (F_DIM / 64)    // 32

__global__ __launch_bounds__(512, 1) void gemm2_h() {
    int e = blockIdx.z;
    int nrows = g_cnt[e];
    int mbase = blockIdx.y * 128;
    if (mbase >= nrows) return;
    int hbase = blockIdx.x * 256;

    extern __shared__ char smem[];
    int* rowpair = (int*)smem;
    uint32_t sb = smem_u32(smem + 1024);

    int tid = threadIdx.x;
    int wid = tid >> 5, lane = tid & 31;
    int g = lane >> 2, tig = lane & 3;
    int wm = wid & 3, wn = wid >> 2;          // 4 x 4 warp grid

    if (tid < 128) {
        int r = mbase + tid;
        rowpair[tid] = (r < nrows) ? g_bucket[e * NPAIR + r] : -1;
    }
    __syncthreads();

    int trow = tid >> 3, tu = tid & 7;
    const __half* aptr[2];
    uint32_t dstA[2];
#pragma unroll
    for (int q = 0; q < 2; q++) {
        int rq = q * 64 + trow;
        int rp = rowpair[rq];
        int pr = (rp >= 0) ? rp : rowpair[0];
        aptr[q] = g_gatedh + (size_t)pr * F_DIM + tu * 8;
        dstA[q] = (uint32_t)(rq * 128 + ((tu ^ (rq & 7)) << 4));
    }
    const __half* bptr[4];
    uint32_t dstB[4];
#pragma unroll
    for (int q = 0; q < 4; q++) {
        int rq = q * 64 + trow;
        bptr[q] = g_w2h + ((size_t)e * H_DIM + hbase + rq) * F_DIM + tu * 8;
        dstB[q] = (uint32_t)(rq * 128 + ((tu ^ (rq & 7)) << 4));
    }

    auto load_chunk = [&](int c, int s) {
        uint32_t base = sb + s * G2_STAGE;
        int ko = c * 64;
#pragma unroll
        for (int q = 0; q < 2; q++) CP16(base + dstA[q], aptr[q] + ko);
#pragma unroll
        for (int q = 0; q < 4; q++) CP16(base + 16384 + dstB[q], bptr[q] + ko);
        CPCOMMIT();
    };

    int lro = ((lane >> 3) & 1) * 8 + (lane & 7);
    int hi = lane >> 4;

    float acc[2][8][4] = {};

    load_chunk(0, 0);
    load_chunk(1, 1);
    for (int c = 0; c < G2_NCH; c++) {
        if (c > 0) __syncthreads();
        if (c + 2 < G2_NCH) load_chunk(c + 2, (c + 2) % 3);
        else                CPCOMMIT();
        CPWAIT(2);
        __syncthreads();

        uint32_t aT = sb + (c % 3) * G2_STAGE;
        uint32_t bT = aT + 16384;
#pragma unroll
        for (int kk = 0; kk < 4; kk++) {
            uint32_t af[2][4];
#pragma unroll
            for (int mf = 0; mf < 2; mf++) {
                int lr = wm * 32 + mf * 16 + lro;
                ldm_x4(af[mf], aT + lr * 128 + ((((kk * 2 + hi)) ^ (lr & 7)) << 4));
            }
            uint32_t bf[4][4];
#pragma unroll
            for (int j = 0; j < 4; j++) {
                int lr = wn * 64 + j * 16 + lro;
                ldm_x4(bf[j], bT + lr * 128 + ((((kk * 2 + hi)) ^ (lr & 7)) << 4));
            }
#pragma unroll
            for (int mf = 0; mf < 2; mf++)
#pragma unroll
                for (int nf = 0; nf < 8; nf++) {
                    int j = nf >> 1, w = nf & 1;
                    mma16(acc[mf][nf], af[mf], bf[j][w], bf[j][w + 2]);
                }
        }
    }

#pragma unroll
    for (int mf = 0; mf < 2; mf++) {
#pragma unroll
        for (int hh = 0; hh < 2; hh++) {
            int row = wm * 32 + mf * 16 + g + hh * 8;
            int p = rowpair[row];
            if (p < 0) continue;
            float* dst = g_y + (size_t)p * H_DIM + hbase;
#pragma unroll
            for (int nf = 0; nf < 8; nf++) {
                int col = wn * 64 + nf * 8 + tig * 2;
                float2 o;
                o.x = acc[mf][nf][hh * 2 + 0];
                o.y = acc[mf][nf][hh * 2 + 1];
                *(float2*)(dst + col) = o;
            }
        }
    }
}

// =================== kernel 4: weighted combine ===================
__global__ void combine_kernel(float* __restrict__ out) {
    int idx = blockIdx.x * blockDim.x + threadIdx.x;
    if (idx >= T_TOK * H_DIM / 4) return;
    int t = idx / (H_DIM / 4);
    int h4 = idx - t * (H_DIM / 4);
    float w0 = g_wpair[2 * t];
    float w1 = g_wpair[2 * t + 1];
    float4 a = *(const float4*)(g_y + (size_t)(2 * t) * H_DIM + h4 * 4);
    float4 b = *(const float4*)(g_y + (size_t)(2 * t + 1) * H_DIM + h4 * 4);
    float4 o;
    o.x = w0 * a.x + w1 * b.x;
    o.y = w0 * a.y + w1 * b.y;
    o.z = w0 * a.z + w1 * b.z;
    o.w = w0 * a.w + w1 * b.w;
    ((float4*)out)[idx] = o;
}

// =================== launch ===================
extern "C" void kernel_launch(void* const* d_in, const int* in_sizes, int n_in,
                              void* d_out, int out_size) {
    const float* hidden = (const float*)d_in[0];
    const float* gate_w = (const float*)d_in[1];
    const float* w1     = (const float*)d_in[2];
    const float* w3     = (const float*)d_in[3];
    const float* w2     = (const float*)d_in[4];
    float* out = (float*)d_out;

    static int attr_done = 0;
    if (!attr_done) {
        cudaFuncSetAttribute(gemm1_h, cudaFuncAttributeMaxDynamicSharedMemorySize, G1_SMEM);
        cudaFuncSetAttribute(gemm2_h, cudaFuncAttributeMaxDynamicSharedMemorySize, G2_SMEM);
        attr_done = 1;
    }

    static void *p_xh = nullptr, *p_w1h, *p_w3h, *p_w2h;
    if (!p_xh) {
        cudaGetSymbolAddress(&p_xh, g_xh);
        cudaGetSymbolAddress(&p_w1h, g_w1h);
        cudaGetSymbolAddress(&p_w3h, g_w3h);
        cudaGetSymbolAddress(&p_w2h, g_w2h);
    }

    const int NW4 = (N_EXP * F_DIM * H_DIM) / 4;
    const int NX4 = (T_TOK * H_DIM) / 4;

    zero_cnt_kernel<<<1, 32>>>();
    f2h_kernel<<<NX4 / 256, 256>>>((const float4*)hidden, (uint2*)p_xh, NX4);
    f2h_kernel<<<NW4 / 256, 256>>>((const float4*)w1, (uint2*)p_w1h, NW4);
    f2h_kernel<<<NW4 / 256, 256>>>((const float4*)w3, (uint2*)p_w3h, NW4);
    f2h_kernel<<<NW4 / 256, 256>>>((const float4*)w2, (uint2*)p_w2h, NW4);
    router_kernel<<<T_TOK / 8, 256>>>(hidden, gate_w, out + RL_OFFSET);
    // worst case one expert owns all NPAIR pairs; extra CTAs exit
    gemm1_h<<<dim3(F_DIM / 64, NPAIR / 256, N_EXP), 512, G1_SMEM>>>();
    gemm2_h<<<dim3(H_DIM / 256, NPAIR / 128, N_EXP), 512, G2_SMEM>>>();
    combine_kernel<<<(T_TOK * H_DIM / 4 + 255) / 256, 256>>>(out);
}

// round 10
// speedup vs baseline: 7.3331x; 1.0272x over previous
#include <cuda_runtime.h>
#include <cuda_fp16.h>
#include <math.h>
#include <stdint.h>

// Problem constants
#define T_TOK  8192
#define H_DIM  1024
#define F_DIM  2048
#define N_EXP  8
#define NPAIR  16384

#define OUT_ELEMS  (T_TOK * H_DIM)
#define RL_OFFSET  OUT_ELEMS

// ---------------- device scratch (static: allocation rules) ----------------
__device__ __half g_xh[(size_t)T_TOK * H_DIM];
__device__ __half g_w1h[(size_t)N_EXP * F_DIM * H_DIM];
__device__ __half g_w3h[(size_t)N_EXP * F_DIM * H_DIM];
__device__ __half g_w2h[(size_t)N_EXP * H_DIM * F_DIM];
__device__ __half g_gatedh[(size_t)NPAIR * F_DIM];
__device__ float  g_y[(size_t)NPAIR * H_DIM];
__device__ int    g_bucket[N_EXP * NPAIR];
__device__ int    g_cnt[N_EXP];
__device__ float  g_wpair[NPAIR];

// =================== PTX helpers (baseline sm_80-class PTX) ===================
__device__ __forceinline__ uint32_t smem_u32(const void* p) {
    uint32_t a;
    asm("{ .reg .u64 t; cvta.to.shared.u64 t, %1; cvt.u32.u64 %0, t; }" : "=r"(a) : "l"(p));
    return a;
}
#define CP16(dst, src) asm volatile("cp.async.cg.shared.global [%0], [%1], 16;" :: "r"(dst), "l"(src))
#define CPCOMMIT()     asm volatile("cp.async.commit_group;")
#define CPWAIT(n)      asm volatile("cp.async.wait_group %0;" :: "n"(n))

__device__ __forceinline__ void ldm_x4(uint32_t* r, uint32_t addr) {
    asm volatile("ldmatrix.sync.aligned.m8n8.x4.shared.b16 {%0,%1,%2,%3}, [%4];"
        : "=r"(r[0]), "=r"(r[1]), "=r"(r[2]), "=r"(r[3]) : "r"(addr));
}
__device__ __forceinline__ void mma16(float* c, const uint32_t* a, uint32_t b0, uint32_t b1) {
    asm volatile(
        "mma.sync.aligned.m16n8k16.row.col.f32.f16.f16.f32 "
        "{%0,%1,%2,%3}, {%4,%5,%6,%7}, {%8,%9}, {%0,%1,%2,%3};"
        : "+f"(c[0]), "+f"(c[1]), "+f"(c[2]), "+f"(c[3])
        : "r"(a[0]), "r"(a[1]), "r"(a[2]), "r"(a[3]), "r"(b0), "r"(b1));
}
// smem tile rows are 128B (64 halfs = BK chunk); phys(row, 16B-unit u) =
// row*128 + ((u ^ (row&7))<<4)  -> conflict-free cp.async + ldmatrix

// =================== kernel 0: zero counters ===================
__global__ void zero_cnt_kernel() {
    if (threadIdx.x < N_EXP) g_cnt[threadIdx.x] = 0;
}

// =================== fused f32 -> f16 (rne) bulk convert ===================
#define NX4 ((T_TOK * H_DIM) / 4)
#define NW4 ((N_EXP * F_DIM * H_DIM) / 4)
#define NCVT (NX4 + 3 * NW4)

__global__ void f2h_all_kernel(const float4* __restrict__ x,
                               const float4* __restrict__ w1,
                               const float4* __restrict__ w3,
                               const float4* __restrict__ w2,
                               uint2* __restrict__ xh, uint2* __restrict__ w1h,
                               uint2* __restrict__ w3h, uint2* __restrict__ w2h) {
    int i = blockIdx.x * blockDim.x + threadIdx.x;
    if (i >= NCVT) return;
    const float4* s;
    uint2* d;
    int j;
    if (i < NX4)               { s = x;  d = xh;  j = i; }
    else if (i < NX4 + NW4)    { s = w1; d = w1h; j = i - NX4; }
    else if (i < NX4 + 2*NW4)  { s = w3; d = w3h; j = i - NX4 - NW4; }
    else                       { s = w2; d = w2h; j = i - NX4 - 2*NW4; }
    float4 v = s[j];
    __half2 h0 = __floats2half2_rn(v.x, v.y);
    __half2 h1 = __floats2half2_rn(v.z, v.w);
    uint2 o;
    o.x = *reinterpret_cast<uint32_t*>(&h0);
    o.y = *reinterpret_cast<uint32_t*>(&h1);
    d[j] = o;
}

// =================== kernel 1: router (f32, exact) ===================
__global__ void router_kernel(const float* __restrict__ x,
                              const float* __restrict__ gw,
                              float* __restrict__ rlogits) {
    int warp = (blockIdx.x * blockDim.x + threadIdx.x) >> 5;
    int lane = threadIdx.x & 31;
    if (warp >= T_TOK) return;

    const float* xr = x + (size_t)warp * H_DIM;
    float xv[32];
#pragma unroll
    for (int i = 0; i < 32; i++) xv[i] = xr[i * 32 + lane];

    float l[N_EXP];
#pragma unroll
    for (int e = 0; e < N_EXP; e++) {
        const float* g = gw + e * H_DIM;
        float s = 0.f;
#pragma unroll
        for (int i = 0; i < 32; i++) s += xv[i] * g[i * 32 + lane];
#pragma unroll
        for (int o = 16; o; o >>= 1) s += __shfl_xor_sync(0xffffffffu, s, o);
        l[e] = s;
    }

    if (lane == 0) {
#pragma unroll
        for (int e = 0; e < N_EXP; e++) rlogits[(size_t)warp * N_EXP + e] = l[e];

        int i0 = 0;
#pragma unroll
        for (int e = 1; e < N_EXP; e++) if (l[e] > l[i0]) i0 = e;
        int i1 = (i0 == 0) ? 1 : 0;
#pragma unroll
        for (int e = 0; e < N_EXP; e++) if (e != i0 && l[e] > l[i1]) i1 = e;

        float e1 = expf(l[i1] - l[i0]);
        float w0 = 1.f / (1.f + e1);
        float w1 = e1 / (1.f + e1);

        int p0 = warp * 2, p1 = warp * 2 + 1;
        g_wpair[p0] = w0;
        g_wpair[p1] = w1;
        int pos0 = atomicAdd(&g_cnt[i0], 1);
        g_bucket[i0 * NPAIR + pos0] = p0;
        int pos1 = atomicAdd(&g_cnt[i1], 1);
        g_bucket[i1 * NPAIR + pos1] = p1;
    }
}

// =================== kernel 2: GEMM1 fp16 (256x64, BK=64, 3-stage) ==========
// CTA: 256 pairs x 64 F-cols. D1 = X W1^T, D3 = X W3^T, silu fuse -> g_gatedh.
// 512 threads = 16 warps (8m x 2n), warp tile 32x32 (dual accum).
// stage (48KB): A 256x128B @0, B1 64x128B @32K, B3 @40K. 3 stages.
// Pipeline: one __syncthreads per chunk; prefetch issued AFTER the barrier
// into the stage of chunk c-1 (provably dead once all threads passed barrier).
#define G1_STAGE 49152
#define G1_SMEM  (1024 + 3 * G1_STAGE)
#define G1_NCH   (H_DIM / 64)    // 16

__global__ __launch_bounds__(512, 1) void gemm1_h() {
    int e = blockIdx.z;
    int nrows = g_cnt[e];
    int mbase = blockIdx.y * 256;
    if (mbase >= nrows) return;
    int fbase = blockIdx.x * 64;

    extern __shared__ char smem[];
    int* rowpair = (int*)smem;
    uint32_t sb = smem_u32(smem + 1024);

    int tid = threadIdx.x;
    int wid = tid >> 5, lane = tid & 31;
    int g = lane >> 2, tig = lane & 3;
    int wm = wid & 7, wn = wid >> 3;          // 8 x 2 warp grid

    if (tid < 256) {
        int r = mbase + tid;
        rowpair[tid] = (r < nrows) ? g_bucket[e * NPAIR + r] : -1;
    }
    __syncthreads();

    // cp.async mapping: trow = tid>>3 (0..63), tu = tid&7
    int trow = tid >> 3, tu = tid & 7;
    const __half* aptr[4];
    uint32_t dstA[4];
#pragma unroll
    for (int q = 0; q < 4; q++) {
        int rq = q * 64 + trow;
        int rp = rowpair[rq];
        int tok = ((rp >= 0) ? rp : rowpair[0]) >> 1;
        aptr[q] = g_xh + (size_t)tok * H_DIM + tu * 8;
        dstA[q] = (uint32_t)(rq * 128 + ((tu ^ (rq & 7)) << 4));
    }
    const __half* b1p = g_w1h + ((size_t)e * F_DIM + fbase + trow) * H_DIM + tu * 8;
    const __half* b3p = g_w3h + ((size_t)e * F_DIM + fbase + trow) * H_DIM + tu * 8;
    uint32_t dstB = (uint32_t)(trow * 128 + ((tu ^ (trow & 7)) << 4));

    auto load_chunk = [&](int c, int s) {
        uint32_t base = sb + s * G1_STAGE;
        int ko = c * 64;
#pragma unroll
        for (int q = 0; q < 4; q++) CP16(base + dstA[q], aptr[q] + ko);
        CP16(base + 32768 + dstB, b1p + ko);
        CP16(base + 40960 + dstB, b3p + ko);
        CPCOMMIT();
    };

    int lro = ((lane >> 3) & 1) * 8 + (lane & 7);
    int hi = lane >> 4;

    float acc1[2][4][4] = {}, acc3[2][4][4] = {};

    load_chunk(0, 0);
    load_chunk(1, 1);
    for (int c = 0; c < G1_NCH; c++) {
        CPWAIT(1);                 // own groups: chunk c landed
        __syncthreads();           // publish chunk c; all done with chunk c-1
        if (c + 2 < G1_NCH) load_chunk(c + 2, (c + 2) % 3);
        else                CPCOMMIT();   // keep group accounting uniform

        uint32_t aT = sb + (c % 3) * G1_STAGE;
        uint32_t b1T = aT + 32768, b3T = aT + 40960;
#pragma unroll
        for (int kk = 0; kk < 4; kk++) {
            uint32_t af[2][4];
#pragma unroll
            for (int mf = 0; mf < 2; mf++) {
                int lr = wm * 32 + mf * 16 + lro;
                ldm_x4(af[mf], aT + lr * 128 + ((((kk * 2 + hi)) ^ (lr & 7)) << 4));
            }
            uint32_t bf1[2][4], bf3[2][4];
#pragma unroll
            for (int j = 0; j < 2; j++) {
                int lr = wn * 32 + j * 16 + lro;
                uint32_t ao = lr * 128 + ((((kk * 2 + hi)) ^ (lr & 7)) << 4);
                ldm_x4(bf1[j], b1T + ao);
                ldm_x4(bf3[j], b3T + ao);
            }
#pragma unroll
            for (int mf = 0; mf < 2; mf++)
#pragma unroll
                for (int nf = 0; nf < 4; nf++) {
                    int j = nf >> 1, w = nf & 1;
                    mma16(acc1[mf][nf], af[mf], bf1[j][w], bf1[j][w + 2]);
                    mma16(acc3[mf][nf], af[mf], bf3[j][w], bf3[j][w + 2]);
                }
        }
    }

    // epilogue: silu(acc1)*acc3 -> g_gatedh (fp16)
#pragma unroll
    for (int mf = 0; mf < 2; mf++) {
#pragma unroll
        for (int hh = 0; hh < 2; hh++) {
            int row = wm * 32 + mf * 16 + g + hh * 8;
            int p = rowpair[row];
            if (p < 0) continue;
            __half* dst = g_gatedh + (size_t)p * F_DIM + fbase;
#pragma unroll
            for (int nf = 0; nf < 4; nf++) {
                int col = wn * 32 + nf * 8 + tig * 2;
                float c0 = acc1[mf][nf][hh * 2 + 0];
                float c1 = acc1[mf][nf][hh * 2 + 1];
                float g0 = acc3[mf][nf][hh * 2 + 0];
                float g1 = acc3[mf][nf][hh * 2 + 1];
                float o0 = c0 / (1.f + expf(-c0)) * g0;
                float o1 = c1 / (1.f + expf(-c1)) * g1;
                *(__half2*)(dst + col) = __floats2half2_rn(o0, o1);
            }
        }
    }
}

// =================== kernel 3: GEMM2 fp16 (128x256, BK=64, 3-stage) =========
// CTA: 128 pairs x 256 H-cols, K = F_DIM.
// 512 threads = 16 warps (4m x 4n), warp tile 32x64.
// stage (48KB): A 128x128B @0, B 256x128B @16K. 3 stages, single-sync.
#define G2_STAGE 49152
#define G2_SMEM  (1024 + 3 * G2_STAGE)
#define G2_NCH   (F_DIM / 64)    // 32

__global__ __launch_bounds__(512, 1) void gemm2_h() {
    int e = blockIdx.z;
    int nrows = g_cnt[e];
    int mbase = blockIdx.y * 128;
    if (mbase >= nrows) return;
    int hbase = blockIdx.x * 256;

    extern __shared__ char smem[];
    int* rowpair = (int*)smem;
    uint32_t sb = smem_u32(smem + 1024);

    int tid = threadIdx.x;
    int wid = tid >> 5, lane = tid & 31;
    int g = lane >> 2, tig = lane & 3;
    int wm = wid & 3, wn = wid >> 2;          // 4 x 4 warp grid

    if (tid < 128) {
        int r = mbase + tid;
        rowpair[tid] = (r < nrows) ? g_bucket[e * NPAIR + r] : -1;
    }
    __syncthreads();

    int trow = tid >> 3, tu = tid & 7;
    const __half* aptr[2];
    uint32_t dstA[2];
#pragma unroll
    for (int q = 0; q < 2; q++) {
        int rq = q * 64 + trow;
        int rp = rowpair[rq];
        int pr = (rp >= 0) ? rp : rowpair[0];
        aptr[q] = g_gatedh + (size_t)pr * F_DIM + tu * 8;
        dstA[q] = (uint32_t)(rq * 128 + ((tu ^ (rq & 7)) << 4));
    }
    const __half* bptr[4];
    uint32_t dstB[4];
#pragma unroll
    for (int q = 0; q < 4; q++) {
        int rq = q * 64 + trow;
        bptr[q] = g_w2h + ((size_t)e * H_DIM + hbase + rq) * F_DIM + tu * 8;
        dstB[q] = (uint32_t)(rq * 128 + ((tu ^ (rq & 7)) << 4));
    }

    auto load_chunk = [&](int c, int s) {
        uint32_t base = sb + s * G2_STAGE;
        int ko = c * 64;
#pragma unroll
        for (int q = 0; q < 2; q++) CP16(base + dstA[q], aptr[q] + ko);
#pragma unroll
        for (int q = 0; q < 4; q++) CP16(base + 16384 + dstB[q], bptr[q] + ko);
        CPCOMMIT();
    };

    int lro = ((lane >> 3) & 1) * 8 + (lane & 7);
    int hi = lane >> 4;

    float acc[2][8][4] = {};

    load_chunk(0, 0);
    load_chunk(1, 1);
    for (int c = 0; c < G2_NCH; c++) {
        CPWAIT(1);
        __syncthreads();
        if (c + 2 < G2_NCH) load_chunk(c + 2, (c + 2) % 3);
        else                CPCOMMIT();

        uint32_t aT = sb + (c % 3) * G2_STAGE;
        uint32_t bT = aT + 16384;
#pragma unroll
        for (int kk = 0; kk < 4; kk++) {
            uint32_t af[2][4];
#pragma unroll
            for (int mf = 0; mf < 2; mf++) {
                int lr = wm * 32 + mf * 16 + lro;
                ldm_x4(af[mf], aT + lr * 128 + ((((kk * 2 + hi)) ^ (lr & 7)) << 4));
            }
            uint32_t bf[4][4];
#pragma unroll
            for (int j = 0; j < 4; j++) {
                int lr = wn * 64 + j * 16 + lro;
                ldm_x4(bf[j], bT + lr * 128 + ((((kk * 2 + hi)) ^ (lr & 7)) << 4));
            }
#pragma unroll
            for (int mf = 0; mf < 2; mf++)
#pragma unroll
                for (int nf = 0; nf < 8; nf++) {
                    int j = nf >> 1, w = nf & 1;
                    mma16(acc[mf][nf], af[mf], bf[j][w], bf[j][w + 2]);
                }
        }
    }

#pragma unroll
    for (int mf = 0; mf < 2; mf++) {
#pragma unroll
        for (int hh = 0; hh < 2; hh++) {
            int row = wm * 32 + mf * 16 + g + hh * 8;
            int p = rowpair[row];
            if (p < 0) continue;
            float* dst = g_y + (size_t)p * H_DIM + hbase;
#pragma unroll
            for (int nf = 0; nf < 8; nf++) {
                int col = wn * 64 + nf * 8 + tig * 2;
                float2 o;
                o.x = acc[mf][nf][hh * 2 + 0];
                o.y = acc[mf][nf][hh * 2 + 1];
                *(float2*)(dst + col) = o;
            }
        }
    }
}

// =================== kernel 4: weighted combine ===================
__global__ void combine_kernel(float* __restrict__ out) {
    int idx = blockIdx.x * blockDim.x + threadIdx.x;
    if (idx >= T_TOK * H_DIM / 4) return;
    int t = idx / (H_DIM / 4);
    int h4 = idx - t * (H_DIM / 4);
    float w0 = g_wpair[2 * t];
    float w1 = g_wpair[2 * t + 1];
    float4 a = *(const float4*)(g_y + (size_t)(2 * t) * H_DIM + h4 * 4);
    float4 b = *(const float4*)(g_y + (size_t)(2 * t + 1) * H_DIM + h4 * 4);
    float4 o;
    o.x = w0 * a.x + w1 * b.x;
    o.y = w0 * a.y + w1 * b.y;
    o.z = w0 * a.z + w1 * b.z;
    o.w = w0 * a.w + w1 * b.w;
    ((float4*)out)[idx] = o;
}

// =================== launch ===================
extern "C" void kernel_launch(void* const* d_in, const int* in_sizes, int n_in,
                              void* d_out, int out_size) {
    const float* hidden = (const float*)d_in[0];
    const float* gate_w = (const float*)d_in[1];
    const float* w1     = (const float*)d_in[2];
    const float* w3     = (const float*)d_in[3];
    const float* w2     = (const float*)d_in[4];
    float* out = (float*)d_out;

    static int attr_done = 0;
    if (!attr_done) {
        cudaFuncSetAttribute(gemm1_h, cudaFuncAttributeMaxDynamicSharedMemorySize, G1_SMEM);
        cudaFuncSetAttribute(gemm2_h, cudaFuncAttributeMaxDynamicSharedMemorySize, G2_SMEM);
        attr_done = 1;
    }

    static void *p_xh = nullptr, *p_w1h, *p_w3h, *p_w2h;
    if (!p_xh) {
        cudaGetSymbolAddress(&p_xh, g_xh);
        cudaGetSymbolAddress(&p_w1h, g_w1h);
        cudaGetSymbolAddress(&p_w3h, g_w3h);
        cudaGetSymbolAddress(&p_w2h, g_w2h);
    }

    zero_cnt_kernel<<<1, 32>>>();
    f2h_all_kernel<<<(NCVT + 255) / 256, 256>>>(
        (const float4*)hidden, (const float4*)w1, (const float4*)w3, (const float4*)w2,
        (uint2*)p_xh, (uint2*)p_w1h, (uint2*)p_w3h, (uint2*)p_w2h);
    router_kernel<<<T_TOK / 8, 256>>>(hidden, gate_w, out + RL_OFFSET);
    // worst case one expert owns all NPAIR pairs; extra CTAs exit
    gemm1_h<<<dim3(F_DIM / 64, NPAIR / 256, N_EXP), 512, G1_SMEM>>>();
    gemm2_h<<<dim3(H_DIM / 256, NPAIR / 128, N_EXP), 512, G2_SMEM>>>();
    combine_kernel<<<(T_TOK * H_DIM / 4 + 255) / 256, 256>>>(out);
}